// round 3
// baseline (speedup 1.0000x reference)
#include <cuda_runtime.h>
#include <math.h>
#include <stdint.h>

// Problem constants
#define BB 32
#define TT 512
#define DD 512
#define UU 1024
#define NC 4096   // 4*U packed gate columns, layout [unit][gate], gate order f,i,g,o

#define NCTA 128      // persistent CTAs (1 per SM)
#define CU 32         // gate-cols per CTA (8 units)
#define NSLICE 16     // K-split factor
#define KSL 64        // k per slice (1024/16)

// -------- device scratch --------
__device__ float g_Whp[1024 * 4096];          // [k][u*4+g] recurrent weights (packed)
__device__ float g_Wxp[512 * 4096];           // [d][u*4+g] input weights (packed)
__device__ float g_bp[4096];                  // packed biases
__device__ float g_zx[(size_t)TT * BB * NC];  // [t][b][u*4+g]  x-part (+bias)
__device__ float g_hT[2][UU * BB];            // ping-pong hidden state, layout [u][b]
__device__ unsigned g_bar;                    // grid barrier counter

// -------- f32x2 helpers --------
__device__ __forceinline__ void fma2(unsigned long long& acc, unsigned long long a,
                                     unsigned long long b) {
    asm("fma.rn.f32x2 %0, %1, %2, %3;" : "=l"(acc) : "l"(a), "l"(b), "l"(acc));
}
__device__ __forceinline__ void add2(unsigned long long& acc, unsigned long long a) {
    asm("add.rn.f32x2 %0, %1, %2;" : "=l"(acc) : "l"(acc), "l"(a));
}
__device__ __forceinline__ unsigned long long dup2(float x) {
    unsigned long long r;
    asm("mov.b64 %0, {%1, %1};" : "=l"(r) : "f"(x));
    return r;
}
__device__ __forceinline__ float2 unpack2(unsigned long long v) {
    float2 r;
    asm("mov.b64 {%0, %1}, %2;" : "=f"(r.x), "=f"(r.y) : "l"(v));
    return r;
}
__device__ __forceinline__ float sigmoidf_(float x) {
    return 1.0f / (1.0f + __expf(-x));
}
__device__ __forceinline__ float tanhf_(float x) {
    // tanh(x) = 1 - 2/(e^{2x}+1); correct saturation at +/-inf of __expf
    return 1.0f - 2.0f / (__expf(2.0f * x) + 1.0f);
}

// -------- barrier primitives (no L1-flushing membar) --------
__device__ __forceinline__ void bar_arrive_release(unsigned* p) {
    unsigned old;
    asm volatile("atom.add.release.gpu.u32 %0, [%1], 1;" : "=r"(old) : "l"(p) : "memory");
}
__device__ __forceinline__ unsigned ld_acquire(unsigned* p) {
    unsigned v;
    asm volatile("ld.acquire.gpu.u32 %0, [%1];" : "=r"(v) : "l"(p) : "memory");
    return v;
}

// ===========================================================================
// Prep: pack weights gate-interleaved, pack biases, zero h0 + barrier
// ===========================================================================
__global__ void prep_kernel(const float* __restrict__ Wf, const float* __restrict__ Wi,
                            const float* __restrict__ Wc, const float* __restrict__ Wo,
                            const float* __restrict__ bf, const float* __restrict__ bi,
                            const float* __restrict__ bc, const float* __restrict__ bo) {
    int idx = blockIdx.x * blockDim.x + threadIdx.x;
    int stride = gridDim.x * blockDim.x;
    if (idx == 0) g_bar = 0u;
    for (int i = idx; i < 1024 * 1024; i += stride) {
        int k = i >> 10, u = i & 1023;
        int s = k * 1024 + u;
        float4 v = make_float4(Wf[s], Wi[s], Wc[s], Wo[s]);
        *(float4*)&g_Whp[((size_t)k << 12) + (u << 2)] = v;
    }
    for (int i = idx; i < 512 * 1024; i += stride) {
        int d = i >> 10, u = i & 1023;
        int s = (1024 + d) * 1024 + u;
        float4 v = make_float4(Wf[s], Wi[s], Wc[s], Wo[s]);
        *(float4*)&g_Wxp[((size_t)d << 12) + (u << 2)] = v;
    }
    for (int u = idx; u < 1024; u += stride)
        *(float4*)&g_bp[u << 2] = make_float4(bf[u], bi[u], bc[u], bo[u]);
    for (int i = idx; i < UU * BB; i += stride) g_hT[0][i] = 0.0f;
}

// ===========================================================================
// zx GEMM:  zx[t][b][c] = bias[c] + sum_d x[b][t][d] * Wxp[d][c]
// 64x64x32 tiles, 256 threads, per-thread 4 rows (2 row-pairs) x 4 cols.
// f32x2 pairs ROWS (free from transposed As); weights pre-duplicated in smem.
// ===========================================================================
#define ZBM 64
#define ZBN 64
#define ZBK 32
#define ZAPAD 68

__global__ __launch_bounds__(256) void zx_kernel(const float* __restrict__ x) {
    __shared__ __align__(16) float As[ZBK][ZAPAD];       // [k][row]
    __shared__ __align__(16) float Bsd[ZBK * 128];       // [k][sel][g][4] dup'd weights 16KB

    int row0 = blockIdx.x * ZBM;
    int c0b = blockIdx.y * ZBN;
    int tid = threadIdx.x;
    int tx = tid & 15;        // col group: cols tx*4..tx*4+3
    int ty = tid >> 4;        // rows ty*4..ty*4+3 (row-pairs 2ty, 2ty+1 local)

    unsigned long long acc[2][4];  // [rowpair][col]
#pragma unroll
    for (int r = 0; r < 2; r++)
#pragma unroll
        for (int c = 0; c < 4; c++) acc[r][c] = 0ull;

    int ar = tid >> 2, akq = tid & 3;   // As staging
    int bkr = tid >> 3, bcq = tid & 7;  // Bsd staging: k=bkr, cols bcq*8..+7

    for (int k0 = 0; k0 < DD; k0 += ZBK) {
        __syncthreads();
        // Stage As (transpose x tile into [k][row])
#pragma unroll
        for (int i = 0; i < 2; i++) {
            int koff = (akq + i * 4) * 4;
            int row = row0 + ar;
            int t = row >> 5, b = row & 31;
            float4 v = *(const float4*)&x[((size_t)b * TT + t) * DD + k0 + koff];
            As[koff + 0][ar] = v.x;
            As[koff + 1][ar] = v.y;
            As[koff + 2][ar] = v.z;
            As[koff + 3][ar] = v.w;
        }
        // Stage Bsd: duplicated weights, layout [k][sel(2)][g(16)][4 floats]
#pragma unroll
        for (int i = 0; i < 2; i++) {
            int c = bcq * 8 + i * 4;      // 4 source cols
            int g = c >> 2;               // chunk index
            float4 v = *(const float4*)&g_Wxp[(size_t)(k0 + bkr) * NC + c0b + c];
            *(float4*)&Bsd[bkr * 128 + 0 + g * 4] = make_float4(v.x, v.x, v.y, v.y);
            *(float4*)&Bsd[bkr * 128 + 64 + g * 4] = make_float4(v.z, v.z, v.w, v.w);
        }
        __syncthreads();

#pragma unroll
        for (int kk = 0; kk < ZBK; kk++) {
            unsigned long long a0 = *(const unsigned long long*)&As[kk][ty * 4];      // rows r0,r1
            unsigned long long a1 = *(const unsigned long long*)&As[kk][ty * 4 + 2];  // rows r2,r3
            ulonglong2 w01 = *(const ulonglong2*)&Bsd[kk * 128 + 0 + tx * 4];   // (c0 dup),(c1 dup)
            ulonglong2 w23 = *(const ulonglong2*)&Bsd[kk * 128 + 64 + tx * 4];  // (c2 dup),(c3 dup)
            fma2(acc[0][0], a0, w01.x); fma2(acc[0][1], a0, w01.y);
            fma2(acc[0][2], a0, w23.x); fma2(acc[0][3], a0, w23.y);
            fma2(acc[1][0], a1, w01.x); fma2(acc[1][1], a1, w01.y);
            fma2(acc[1][2], a1, w23.x); fma2(acc[1][3], a1, w23.y);
        }
    }

    float4 bias = *(const float4*)&g_bp[c0b + tx * 4];
#pragma unroll
    for (int rp = 0; rp < 2; rp++) {
        float2 v0 = unpack2(acc[rp][0]);
        float2 v1 = unpack2(acc[rp][1]);
        float2 v2 = unpack2(acc[rp][2]);
        float2 v3 = unpack2(acc[rp][3]);
        int r = row0 + ty * 4 + rp * 2;
        float4 oA = make_float4(v0.x + bias.x, v1.x + bias.y, v2.x + bias.z, v3.x + bias.w);
        float4 oB = make_float4(v0.y + bias.x, v1.y + bias.y, v2.y + bias.z, v3.y + bias.w);
        *(float4*)&g_zx[(size_t)r * NC + c0b + tx * 4] = oA;
        *(float4*)&g_zx[(size_t)(r + 1) * NC + c0b + tx * 4] = oB;
    }
}

// ===========================================================================
// Persistent recurrent kernel: 512 threads x 128 CTAs, all 512 timesteps.
// CTA cu owns gate-cols [32cu, 32cu+32) (units 8cu..8cu+7).
// Weights resident in smem (128 KB). K-split 16 x 64k; per-thread 2b x 16c.
// smem: ws[1024][32] (128KB) + red[16][16][32] ull (64KB) = 192KB
// ===========================================================================
__global__ __launch_bounds__(512, 1) void lstm_persistent(float* __restrict__ out) {
    extern __shared__ __align__(16) float smem[];
    float* ws = smem;                                                   // 128KB
    unsigned long long* red = (unsigned long long*)(smem + 1024 * 32);  // 64KB

    const int tid = threadIdx.x;
    const int cu = blockIdx.x;

    // --- load this CTA's weight slice into smem (once) ---
    {
        const float4* src = (const float4*)(g_Whp + (size_t)cu * CU);
        float4* dst = (float4*)ws;
        for (int i = tid; i < 1024 * 8; i += 512) {
            int k = i >> 3, q = i & 7;
            dst[k * 8 + q] = src[(size_t)k * 1024 + q];
        }
    }

    // --- GEMM roles ---
    const int s = tid >> 5;          // k-slice 0..15
    const int lane = tid & 31;
    const int cg = lane >> 4;        // col group (16 cols): c0 = cg*16
    const int bp = lane & 15;        // batch pair: batches 2bp, 2bp+1
    const int kb = s * KSL;
    const int c0 = cg * 16;

    // --- gate-math roles (tid < 256) ---
    const int up = (tid >> 5) & 7;   // unit-in-CTA 0..7
    const int gb = tid & 31;         // batch 0..31
    const int ug = cu * 8 + up;      // global unit

    float c_state = 0.0f;

    __syncthreads();                 // weights ready

    for (int t = 0; t < TT; t++) {
        const float* __restrict__ hT = g_hT[t & 1];
        float* __restrict__ hTo = g_hT[(t + 1) & 1];

        // Prefetch zx for this step early (hides L2 latency behind GEMM)
        float4 zx4 = make_float4(0.f, 0.f, 0.f, 0.f);
        if (tid < 256)
            zx4 = __ldcg((const float4*)&g_zx[((size_t)t * BB + gb) * NC + ug * 4]);

        // ---- GEMM: acc[bi][cp] over k in [kb, kb+64) ----
        unsigned long long acc[2][8];
#pragma unroll
        for (int bi = 0; bi < 2; bi++)
#pragma unroll
            for (int p = 0; p < 8; p++) acc[bi][p] = 0ull;

        const float2* hp = (const float2*)(hT + (size_t)kb * 32) + bp;  // stride 16 float2 per k
        const float* wrow0 = ws + kb * 32 + c0;

        float2 bufA[4], bufB[4];
#pragma unroll
        for (int j = 0; j < 4; j++) bufA[j] = __ldcg(hp + (size_t)j * 16);

#pragma unroll
        for (int kc = 0; kc < KSL; kc += 8) {
#pragma unroll
            for (int j = 0; j < 4; j++) bufB[j] = __ldcg(hp + (size_t)(kc + 4 + j) * 16);
#pragma unroll
            for (int j = 0; j < 4; j++) {
                float2 hv = bufA[j];
                unsigned long long h0 = dup2(hv.x), h1 = dup2(hv.y);
                const ulonglong2* wr = (const ulonglong2*)(wrow0 + (size_t)(kc + j) * 32);
#pragma unroll
                for (int q = 0; q < 2; q++) {
                    ulonglong2 wa = wr[2 * q];
                    ulonglong2 wb = wr[2 * q + 1];
                    fma2(acc[0][4 * q + 0], h0, wa.x); fma2(acc[0][4 * q + 1], h0, wa.y);
                    fma2(acc[0][4 * q + 2], h0, wb.x); fma2(acc[0][4 * q + 3], h0, wb.y);
                    fma2(acc[1][4 * q + 0], h1, wa.x); fma2(acc[1][4 * q + 1], h1, wa.y);
                    fma2(acc[1][4 * q + 2], h1, wb.x); fma2(acc[1][4 * q + 3], h1, wb.y);
                }
            }
            if (kc + 8 < KSL) {
#pragma unroll
                for (int j = 0; j < 4; j++) bufA[j] = __ldcg(hp + (size_t)(kc + 8 + j) * 16);
            }
#pragma unroll
            for (int j = 0; j < 4; j++) {
                float2 hv = bufB[j];
                unsigned long long h0 = dup2(hv.x), h1 = dup2(hv.y);
                const ulonglong2* wr = (const ulonglong2*)(wrow0 + (size_t)(kc + 4 + j) * 32);
#pragma unroll
                for (int q = 0; q < 2; q++) {
                    ulonglong2 wa = wr[2 * q];
                    ulonglong2 wb = wr[2 * q + 1];
                    fma2(acc[0][4 * q + 0], h0, wa.x); fma2(acc[0][4 * q + 1], h0, wa.y);
                    fma2(acc[0][4 * q + 2], h0, wb.x); fma2(acc[0][4 * q + 3], h0, wb.y);
                    fma2(acc[1][4 * q + 0], h1, wa.x); fma2(acc[1][4 * q + 1], h1, wa.y);
                    fma2(acc[1][4 * q + 2], h1, wb.x); fma2(acc[1][4 * q + 3], h1, wb.y);
                }
            }
        }

        // ---- write partials: red[s][cp_global][b] (ull = colpair value for batch b) ----
#pragma unroll
        for (int bi = 0; bi < 2; bi++)
#pragma unroll
            for (int p = 0; p < 8; p++)
                red[((size_t)s * 16 + cg * 8 + p) * 32 + 2 * bp + bi] = acc[bi][p];
        __syncthreads();

        // ---- reduce + gate math (threads 0..255: one (unit, batch) each) ----
        float h_new = 0.0f;
        if (tid < 256) {
            unsigned long long fiv = 0ull, gov = 0ull;
#pragma unroll
            for (int ss = 0; ss < NSLICE; ss++) {
                add2(fiv, red[((size_t)ss * 16 + 2 * up) * 32 + gb]);
                add2(gov, red[((size_t)ss * 16 + 2 * up + 1) * 32 + gb]);
            }
            float2 fi = unpack2(fiv);
            float2 go = unpack2(gov);
            float zf = fi.x + zx4.x;
            float zi = fi.y + zx4.y;
            float zg = go.x + zx4.z;
            float zo = go.y + zx4.w;

            float f = sigmoidf_(zf);
            float ii = sigmoidf_(zi);
            float g = tanhf_(zg);
            float o = sigmoidf_(zo);
            c_state = f * c_state + ii * g;
            h_new = o * tanhf_(c_state);

            __stcg(&hTo[ug * 32 + gb], h_new);
        }

        // ---- grid barrier (release/acquire; no L1-flushing membar) ----
        __syncthreads();   // all h stores issued, red consumed
        if (tid == 0) bar_arrive_release(&g_bar);

        // Overlap with barrier: out[] store (no cross-CTA consumer)
        if (tid < 256)
            out[((size_t)gb * TT + t) * UU + ug] = h_new;

        if (tid == 0) {
            unsigned target = (unsigned)NCTA * (unsigned)(t + 1);
            while (ld_acquire(&g_bar) < target) {}
        }
        __syncthreads();
    }
}

// ===========================================================================
// Launch
// ===========================================================================
extern "C" void kernel_launch(void* const* d_in, const int* in_sizes, int n_in,
                              void* d_out, int out_size) {
    const float* data = (const float*)d_in[0];
    const float* Wf = (const float*)d_in[1];
    const float* bf = (const float*)d_in[2];
    const float* Wi = (const float*)d_in[3];
    const float* bi = (const float*)d_in[4];
    const float* Wc = (const float*)d_in[5];
    const float* bc = (const float*)d_in[6];
    const float* Wo = (const float*)d_in[7];
    const float* bo = (const float*)d_in[8];
    float* out = (float*)d_out;

    prep_kernel<<<512, 256>>>(Wf, Wi, Wc, Wo, bf, bi, bc, bo);

    dim3 zgrid(TT * BB / ZBM, NC / ZBN);
    zx_kernel<<<zgrid, 256>>>(data);

    static int smem_set = 0;
    const int smem_bytes = 1024 * 32 * 4 + 16 * 16 * 32 * 8;  // 128KB + 64KB = 192KB
    if (!smem_set) {
        cudaFuncSetAttribute(lstm_persistent,
                             cudaFuncAttributeMaxDynamicSharedMemorySize, smem_bytes);
        smem_set = 1;
    }
    lstm_persistent<<<NCTA, 512, smem_bytes>>>(out);
}

// round 4
// speedup vs baseline: 1.2204x; 1.2204x over previous
#include <cuda_runtime.h>
#include <math.h>
#include <stdint.h>

// Problem constants
#define BB 32
#define TT 512
#define DD 512
#define UU 1024
#define NC 4096   // 4*U packed gate columns, layout [unit][gate], gate order f,i,g,o

#define NCTA 128      // persistent CTAs (1 per SM)
#define CU 32         // gate-cols per CTA (8 units)
#define NSLICE 16     // K-split factor
#define KSL 64        // k per slice (1024/16)

// -------- device scratch --------
__device__ float g_Whp[1024 * 4096];          // [k][u*4+g] recurrent weights (packed)
__device__ float g_Wxp[512 * 4096];           // [d][u*4+g] input weights (packed)
__device__ float g_bp[4096];                  // packed biases
__device__ float g_zx[(size_t)TT * BB * NC];  // [t][b][u*4+g]  x-part (+bias)
__device__ float g_hT[2][UU * BB];            // ping-pong hidden state, layout [u][b]
__device__ unsigned g_bar;                    // grid barrier counter

// -------- f32x2 helpers --------
__device__ __forceinline__ void fma2(unsigned long long& acc, unsigned long long a,
                                     unsigned long long b) {
    asm("fma.rn.f32x2 %0, %1, %2, %3;" : "=l"(acc) : "l"(a), "l"(b), "l"(acc));
}
__device__ __forceinline__ void add2(unsigned long long& acc, unsigned long long a) {
    asm("add.rn.f32x2 %0, %1, %2;" : "=l"(acc) : "l"(acc), "l"(a));
}
__device__ __forceinline__ unsigned long long dup2(float x) {
    unsigned long long r;
    asm("mov.b64 %0, {%1, %1};" : "=l"(r) : "f"(x));
    return r;
}
__device__ __forceinline__ float2 unpack2(unsigned long long v) {
    float2 r;
    asm("mov.b64 {%0, %1}, %2;" : "=f"(r.x), "=f"(r.y) : "l"(v));
    return r;
}
__device__ __forceinline__ float sigmoidf_(float x) {
    return 1.0f / (1.0f + __expf(-x));
}

// -------- barrier primitives (no L1-flushing membar) --------
__device__ __forceinline__ void bar_arrive_release(unsigned* p) {
    unsigned old;
    asm volatile("atom.add.release.gpu.u32 %0, [%1], 1;" : "=r"(old) : "l"(p) : "memory");
}
__device__ __forceinline__ unsigned ld_acquire(unsigned* p) {
    unsigned v;
    asm volatile("ld.acquire.gpu.u32 %0, [%1];" : "=r"(v) : "l"(p) : "memory");
    return v;
}

// ===========================================================================
// Prep: pack weights gate-interleaved, pack biases, zero h0 + barrier
// ===========================================================================
__global__ void prep_kernel(const float* __restrict__ Wf, const float* __restrict__ Wi,
                            const float* __restrict__ Wc, const float* __restrict__ Wo,
                            const float* __restrict__ bf, const float* __restrict__ bi,
                            const float* __restrict__ bc, const float* __restrict__ bo) {
    int idx = blockIdx.x * blockDim.x + threadIdx.x;
    int stride = gridDim.x * blockDim.x;
    if (idx == 0) g_bar = 0u;
    for (int i = idx; i < 1024 * 1024; i += stride) {
        int k = i >> 10, u = i & 1023;
        int s = k * 1024 + u;
        float4 v = make_float4(Wf[s], Wi[s], Wc[s], Wo[s]);
        *(float4*)&g_Whp[((size_t)k << 12) + (u << 2)] = v;
    }
    for (int i = idx; i < 512 * 1024; i += stride) {
        int d = i >> 10, u = i & 1023;
        int s = (1024 + d) * 1024 + u;
        float4 v = make_float4(Wf[s], Wi[s], Wc[s], Wo[s]);
        *(float4*)&g_Wxp[((size_t)d << 12) + (u << 2)] = v;
    }
    for (int u = idx; u < 1024; u += stride)
        *(float4*)&g_bp[u << 2] = make_float4(bf[u], bi[u], bc[u], bo[u]);
    for (int i = idx; i < UU * BB; i += stride) g_hT[0][i] = 0.0f;
}

// ===========================================================================
// zx GEMM (identical to the 5766us R2 version):
//   zx[t][b][c] = bias[c] + sum_d x[b][t][d] * Wxp[d][c]
// ===========================================================================
#define ZBM 64
#define ZBN 64
#define ZBK 32
#define ZAPAD 68

__global__ __launch_bounds__(256) void zx_kernel(const float* __restrict__ x) {
    __shared__ __align__(16) float As[ZBK][ZAPAD];
    __shared__ __align__(16) float Bs[ZBK][ZBN];

    int row0 = blockIdx.x * ZBM;
    int c0 = blockIdx.y * ZBN;
    int tid = threadIdx.x;
    int tx = tid & 15;
    int ty = tid >> 4;

    unsigned long long acc01[4], acc23[4];
#pragma unroll
    for (int r = 0; r < 4; r++) { acc01[r] = 0ull; acc23[r] = 0ull; }

    int ar = tid >> 2, akq = tid & 3;
    int bkr = tid >> 3, bcq = tid & 7;

    for (int k0 = 0; k0 < DD; k0 += ZBK) {
        __syncthreads();
#pragma unroll
        for (int i = 0; i < 2; i++) {
            int koff = (akq + i * 4) * 4;
            int row = row0 + ar;
            int t = row >> 5, b = row & 31;
            float4 v = *(const float4*)&x[((size_t)b * TT + t) * DD + k0 + koff];
            As[koff + 0][ar] = v.x;
            As[koff + 1][ar] = v.y;
            As[koff + 2][ar] = v.z;
            As[koff + 3][ar] = v.w;
        }
#pragma unroll
        for (int i = 0; i < 2; i++) {
            int coff = (bcq + i * 8) * 4;
            float4 v = *(const float4*)&g_Wxp[(size_t)(k0 + bkr) * NC + c0 + coff];
            *(float4*)&Bs[bkr][coff] = v;
        }
        __syncthreads();

#pragma unroll
        for (int kk = 0; kk < ZBK; kk++) {
            float4 a = *(const float4*)&As[kk][ty * 4];
            ulonglong2 bv = *(const ulonglong2*)&Bs[kk][tx * 4];
            unsigned long long a0 = dup2(a.x);
            unsigned long long a1 = dup2(a.y);
            unsigned long long a2 = dup2(a.z);
            unsigned long long a3 = dup2(a.w);
            fma2(acc01[0], a0, bv.x); fma2(acc23[0], a0, bv.y);
            fma2(acc01[1], a1, bv.x); fma2(acc23[1], a1, bv.y);
            fma2(acc01[2], a2, bv.x); fma2(acc23[2], a2, bv.y);
            fma2(acc01[3], a3, bv.x); fma2(acc23[3], a3, bv.y);
        }
    }

    float4 bias = *(const float4*)&g_bp[c0 + tx * 4];
#pragma unroll
    for (int r = 0; r < 4; r++) {
        float2 v01 = unpack2(acc01[r]);
        float2 v23 = unpack2(acc23[r]);
        float4 o;
        o.x = v01.x + bias.x;
        o.y = v01.y + bias.y;
        o.z = v23.x + bias.z;
        o.w = v23.y + bias.w;
        int row = row0 + ty * 4 + r;
        *(float4*)&g_zx[(size_t)row * NC + c0 + tx * 4] = o;
    }
}

// ===========================================================================
// Persistent recurrent kernel (R2 structure: 256 threads, 2 warps/SMSP).
// Changes vs R2: release/acquire barrier (no L1 flush), zx prefetched at
// step top via __ldcg, out[] store overlapped with barrier wait.
// smem: ws[1024][32] (128KB) + red[16][16][32] ull (64KB) = 192KB
// ===========================================================================
__global__ __launch_bounds__(256, 1) void lstm_persistent(float* __restrict__ out) {
    extern __shared__ __align__(16) float smem[];
    float* ws = smem;                                                   // 128KB
    unsigned long long* red = (unsigned long long*)(smem + 1024 * 32);  // 64KB

    const int tid = threadIdx.x;
    const int cu = blockIdx.x;

    // --- load this CTA's weight slice into smem (once) ---
    {
        const float4* src = (const float4*)(g_Whp + (size_t)cu * CU);
        float4* dst = (float4*)ws;
        for (int i = tid; i < 1024 * 8; i += 256) {
            int k = i >> 3, q = i & 7;
            dst[k * 8 + q] = src[(size_t)k * 1024 + q];
        }
    }

    // --- GEMM roles (R2) ---
    const int s = tid >> 4;          // k-slice 0..15
    const int cov = tid & 15;
    const int bg = cov & 7;          // batch group (4 batches)
    const int cg = cov >> 3;         // col group (16 cols)
    const int b0 = bg * 4;
    const int c0 = cg * 16;
    const int kb = s * KSL;

    // --- gate-math roles ---
    const int up = tid >> 5;         // unit-in-CTA 0..7
    const int gb = tid & 31;         // batch 0..31
    const int ug = cu * 8 + up;      // global unit

    float c_state = 0.0f;

    __syncthreads();                 // weights ready

    for (int t = 0; t < TT; t++) {
        const float* __restrict__ hT = g_hT[t & 1];
        float* __restrict__ hTo = g_hT[(t + 1) & 1];

        // Prefetch zx for this step (hidden behind the GEMM)
        float4 zx4 = __ldcg((const float4*)&g_zx[((size_t)t * BB + gb) * NC + ug * 4]);

        // ---- GEMM: acc[b][cp] over k in [kb, kb+64) ----
        unsigned long long acc[4][8];
#pragma unroll
        for (int b = 0; b < 4; b++)
#pragma unroll
            for (int p = 0; p < 8; p++) acc[b][p] = 0ull;

        const float4* hp = (const float4*)(hT + (size_t)kb * 32 + b0);
        const ulonglong2* wrow0 = (const ulonglong2*)(ws + kb * 32 + c0);

        float4 bufA[4], bufB[4];
#pragma unroll
        for (int j = 0; j < 4; j++) bufA[j] = __ldcg(hp + (size_t)j * 8);

#pragma unroll
        for (int kc = 0; kc < KSL; kc += 8) {
#pragma unroll
            for (int j = 0; j < 4; j++) bufB[j] = __ldcg(hp + (size_t)(kc + 4 + j) * 8);
#pragma unroll
            for (int j = 0; j < 4; j++) {
                float4 hv = bufA[j];
                unsigned long long h0 = dup2(hv.x), h1 = dup2(hv.y);
                unsigned long long h2 = dup2(hv.z), h3 = dup2(hv.w);
                const ulonglong2* wr = wrow0 + (size_t)(kc + j) * 8;
#pragma unroll
                for (int q = 0; q < 4; q++) {
                    ulonglong2 w2 = wr[q];
                    fma2(acc[0][2 * q], h0, w2.x); fma2(acc[0][2 * q + 1], h0, w2.y);
                    fma2(acc[1][2 * q], h1, w2.x); fma2(acc[1][2 * q + 1], h1, w2.y);
                    fma2(acc[2][2 * q], h2, w2.x); fma2(acc[2][2 * q + 1], h2, w2.y);
                    fma2(acc[3][2 * q], h3, w2.x); fma2(acc[3][2 * q + 1], h3, w2.y);
                }
            }
            if (kc + 8 < KSL) {
#pragma unroll
                for (int j = 0; j < 4; j++) bufA[j] = __ldcg(hp + (size_t)(kc + 8 + j) * 8);
            }
#pragma unroll
            for (int j = 0; j < 4; j++) {
                float4 hv = bufB[j];
                unsigned long long h0 = dup2(hv.x), h1 = dup2(hv.y);
                unsigned long long h2 = dup2(hv.z), h3 = dup2(hv.w);
                const ulonglong2* wr = wrow0 + (size_t)(kc + 4 + j) * 8;
#pragma unroll
                for (int q = 0; q < 4; q++) {
                    ulonglong2 w2 = wr[q];
                    fma2(acc[0][2 * q], h0, w2.x); fma2(acc[0][2 * q + 1], h0, w2.y);
                    fma2(acc[1][2 * q], h1, w2.x); fma2(acc[1][2 * q + 1], h1, w2.y);
                    fma2(acc[2][2 * q], h2, w2.x); fma2(acc[2][2 * q + 1], h2, w2.y);
                    fma2(acc[3][2 * q], h3, w2.x); fma2(acc[3][2 * q + 1], h3, w2.y);
                }
            }
        }

        // ---- write partials: red[s][cp_global][b] ----
#pragma unroll
        for (int b = 0; b < 4; b++)
#pragma unroll
            for (int p = 0; p < 8; p++)
                red[((size_t)s * 16 + cg * 8 + p) * 32 + b0 + b] = acc[b][p];
        __syncthreads();

        // ---- reduce + gate math: thread = (unit up, batch gb) ----
        float h_new;
        {
            unsigned long long fiv = 0ull, gov = 0ull;
#pragma unroll
            for (int ss = 0; ss < NSLICE; ss++) {
                add2(fiv, red[((size_t)ss * 16 + 2 * up) * 32 + gb]);
                add2(gov, red[((size_t)ss * 16 + 2 * up + 1) * 32 + gb]);
            }
            float2 fi = unpack2(fiv);
            float2 go = unpack2(gov);
            float zf = fi.x + zx4.x;
            float zi = fi.y + zx4.y;
            float zg = go.x + zx4.z;
            float zo = go.y + zx4.w;

            float f = sigmoidf_(zf);
            float ii = sigmoidf_(zi);
            float g = tanhf(zg);
            float o = sigmoidf_(zo);
            c_state = f * c_state + ii * g;
            h_new = o * tanhf(c_state);

            __stcg(&hTo[ug * 32 + gb], h_new);
        }

        // ---- grid barrier (release/acquire; no L1-flushing membar) ----
        __syncthreads();   // all h stores issued, red consumed
        if (tid == 0) bar_arrive_release(&g_bar);

        // Overlap with barrier: out[] store (no cross-CTA consumer)
        out[((size_t)gb * TT + t) * UU + ug] = h_new;

        if (tid == 0) {
            unsigned target = (unsigned)NCTA * (unsigned)(t + 1);
            while (ld_acquire(&g_bar) < target) {}
        }
        __syncthreads();
    }
}

// ===========================================================================
// Launch
// ===========================================================================
extern "C" void kernel_launch(void* const* d_in, const int* in_sizes, int n_in,
                              void* d_out, int out_size) {
    const float* data = (const float*)d_in[0];
    const float* Wf = (const float*)d_in[1];
    const float* bf = (const float*)d_in[2];
    const float* Wi = (const float*)d_in[3];
    const float* bi = (const float*)d_in[4];
    const float* Wc = (const float*)d_in[5];
    const float* bc = (const float*)d_in[6];
    const float* Wo = (const float*)d_in[7];
    const float* bo = (const float*)d_in[8];
    float* out = (float*)d_out;

    prep_kernel<<<512, 256>>>(Wf, Wi, Wc, Wo, bf, bi, bc, bo);

    dim3 zgrid(TT * BB / ZBM, NC / ZBN);
    zx_kernel<<<zgrid, 256>>>(data);

    static int smem_set = 0;
    const int smem_bytes = 1024 * 32 * 4 + 16 * 16 * 32 * 8;  // 128KB + 64KB = 192KB
    if (!smem_set) {
        cudaFuncSetAttribute(lstm_persistent,
                             cudaFuncAttributeMaxDynamicSharedMemorySize, smem_bytes);
        smem_set = 1;
    }
    lstm_persistent<<<NCTA, 256, smem_bytes>>>(out);
}

// round 5
// speedup vs baseline: 1.2411x; 1.0170x over previous
#include <cuda_runtime.h>
#include <math.h>
#include <stdint.h>

// Problem constants
#define BB 32
#define TT 512
#define DD 512
#define UU 1024
#define NC 4096   // 4*U packed gate columns, layout [unit][gate], gate order f,i,g,o

#define NCTA 128      // persistent CTAs (1 per SM)
#define CU 32         // gate-cols per CTA (8 units)
#define NSLICE 16     // K-split factor
#define KSL 64        // k per slice (1024/16)

// -------- device scratch --------
__device__ float g_Whp[1024 * 4096];          // [k][u*4+g] recurrent weights (packed)
__device__ float g_Wxp[512 * 4096];           // [d][u*4+g] input weights (packed)
__device__ float g_bp[4096];                  // packed biases
__device__ float g_zx[(size_t)TT * BB * NC];  // [t][b][u*4+g]  x-part (+bias)
__device__ float g_hT[2][UU * BB];            // ping-pong hidden state, layout [u][b]
__device__ unsigned g_bar;                    // grid barrier counter

// -------- f32x2 helpers --------
__device__ __forceinline__ void fma2(unsigned long long& acc, unsigned long long a,
                                     unsigned long long b) {
    asm("fma.rn.f32x2 %0, %1, %2, %3;" : "=l"(acc) : "l"(a), "l"(b), "l"(acc));
}
__device__ __forceinline__ void add2(unsigned long long& acc, unsigned long long a) {
    asm("add.rn.f32x2 %0, %1, %2;" : "=l"(acc) : "l"(acc), "l"(a));
}
__device__ __forceinline__ unsigned long long dup2(float x) {
    unsigned long long r;
    asm("mov.b64 %0, {%1, %1};" : "=l"(r) : "f"(x));
    return r;
}
__device__ __forceinline__ float2 unpack2(unsigned long long v) {
    float2 r;
    asm("mov.b64 {%0, %1}, %2;" : "=f"(r.x), "=f"(r.y) : "l"(v));
    return r;
}
__device__ __forceinline__ float sigmoidf_(float x) {
    return 1.0f / (1.0f + __expf(-x));
}
__device__ __forceinline__ float tanhf_(float x) {
    // tanh(x) = 1 - 2/(e^{2x}+1); saturates correctly at +/-inf via __expf
    return 1.0f - 2.0f / (__expf(2.0f * x) + 1.0f);
}

// -------- barrier primitives (no L1-flushing membar) --------
__device__ __forceinline__ void bar_arrive_release(unsigned* p) {
    unsigned old;
    asm volatile("atom.add.release.gpu.u32 %0, [%1], 1;" : "=r"(old) : "l"(p) : "memory");
}
__device__ __forceinline__ unsigned ld_acquire(unsigned* p) {
    unsigned v;
    asm volatile("ld.acquire.gpu.u32 %0, [%1];" : "=r"(v) : "l"(p) : "memory");
    return v;
}

// ===========================================================================
// Prep: pack weights gate-interleaved, pack biases, zero h0 + barrier
// ===========================================================================
__global__ void prep_kernel(const float* __restrict__ Wf, const float* __restrict__ Wi,
                            const float* __restrict__ Wc, const float* __restrict__ Wo,
                            const float* __restrict__ bf, const float* __restrict__ bi,
                            const float* __restrict__ bc, const float* __restrict__ bo) {
    int idx = blockIdx.x * blockDim.x + threadIdx.x;
    int stride = gridDim.x * blockDim.x;
    if (idx == 0) g_bar = 0u;
    for (int i = idx; i < 1024 * 1024; i += stride) {
        int k = i >> 10, u = i & 1023;
        int s = k * 1024 + u;
        float4 v = make_float4(Wf[s], Wi[s], Wc[s], Wo[s]);
        *(float4*)&g_Whp[((size_t)k << 12) + (u << 2)] = v;
    }
    for (int i = idx; i < 512 * 1024; i += stride) {
        int d = i >> 10, u = i & 1023;
        int s = (1024 + d) * 1024 + u;
        float4 v = make_float4(Wf[s], Wi[s], Wc[s], Wo[s]);
        *(float4*)&g_Wxp[((size_t)d << 12) + (u << 2)] = v;
    }
    for (int u = idx; u < 1024; u += stride)
        *(float4*)&g_bp[u << 2] = make_float4(bf[u], bi[u], bc[u], bo[u]);
    for (int i = idx; i < UU * BB; i += stride) g_hT[0][i] = 0.0f;
}

// ===========================================================================
// zx GEMM (unchanged from the 5489us R4 version):
//   zx[t][b][c] = bias[c] + sum_d x[b][t][d] * Wxp[d][c]
// ===========================================================================
#define ZBM 64
#define ZBN 64
#define ZBK 32
#define ZAPAD 68

__global__ __launch_bounds__(256) void zx_kernel(const float* __restrict__ x) {
    __shared__ __align__(16) float As[ZBK][ZAPAD];
    __shared__ __align__(16) float Bs[ZBK][ZBN];

    int row0 = blockIdx.x * ZBM;
    int c0 = blockIdx.y * ZBN;
    int tid = threadIdx.x;
    int tx = tid & 15;
    int ty = tid >> 4;

    unsigned long long acc01[4], acc23[4];
#pragma unroll
    for (int r = 0; r < 4; r++) { acc01[r] = 0ull; acc23[r] = 0ull; }

    int ar = tid >> 2, akq = tid & 3;
    int bkr = tid >> 3, bcq = tid & 7;

    for (int k0 = 0; k0 < DD; k0 += ZBK) {
        __syncthreads();
#pragma unroll
        for (int i = 0; i < 2; i++) {
            int koff = (akq + i * 4) * 4;
            int row = row0 + ar;
            int t = row >> 5, b = row & 31;
            float4 v = *(const float4*)&x[((size_t)b * TT + t) * DD + k0 + koff];
            As[koff + 0][ar] = v.x;
            As[koff + 1][ar] = v.y;
            As[koff + 2][ar] = v.z;
            As[koff + 3][ar] = v.w;
        }
#pragma unroll
        for (int i = 0; i < 2; i++) {
            int coff = (bcq + i * 8) * 4;
            float4 v = *(const float4*)&g_Wxp[(size_t)(k0 + bkr) * NC + c0 + coff];
            *(float4*)&Bs[bkr][coff] = v;
        }
        __syncthreads();

#pragma unroll
        for (int kk = 0; kk < ZBK; kk++) {
            float4 a = *(const float4*)&As[kk][ty * 4];
            ulonglong2 bv = *(const ulonglong2*)&Bs[kk][tx * 4];
            unsigned long long a0 = dup2(a.x);
            unsigned long long a1 = dup2(a.y);
            unsigned long long a2 = dup2(a.z);
            unsigned long long a3 = dup2(a.w);
            fma2(acc01[0], a0, bv.x); fma2(acc23[0], a0, bv.y);
            fma2(acc01[1], a1, bv.x); fma2(acc23[1], a1, bv.y);
            fma2(acc01[2], a2, bv.x); fma2(acc23[2], a2, bv.y);
            fma2(acc01[3], a3, bv.x); fma2(acc23[3], a3, bv.y);
        }
    }

    float4 bias = *(const float4*)&g_bp[c0 + tx * 4];
#pragma unroll
    for (int r = 0; r < 4; r++) {
        float2 v01 = unpack2(acc01[r]);
        float2 v23 = unpack2(acc23[r]);
        float4 o;
        o.x = v01.x + bias.x;
        o.y = v01.y + bias.y;
        o.z = v23.x + bias.z;
        o.w = v23.y + bias.w;
        int row = row0 + ty * 4 + r;
        *(float4*)&g_zx[(size_t)row * NC + c0 + tx * 4] = o;
    }
}

// ===========================================================================
// Persistent recurrent kernel (R4 structure: 256 threads, 2 warps/SMSP).
// Changes vs R4: h prefetch depth doubled to 8 k-iters (covers queued L2
// latency ~580 cyc); fast tanh on the serial tail.
// smem: ws[1024][32] (128KB) + red[16][16][32] ull (64KB) = 192KB
// ===========================================================================
__global__ __launch_bounds__(256, 1) void lstm_persistent(float* __restrict__ out) {
    extern __shared__ __align__(16) float smem[];
    float* ws = smem;                                                   // 128KB
    unsigned long long* red = (unsigned long long*)(smem + 1024 * 32);  // 64KB

    const int tid = threadIdx.x;
    const int cu = blockIdx.x;

    // --- load this CTA's weight slice into smem (once) ---
    {
        const float4* src = (const float4*)(g_Whp + (size_t)cu * CU);
        float4* dst = (float4*)ws;
        for (int i = tid; i < 1024 * 8; i += 256) {
            int k = i >> 3, q = i & 7;
            dst[k * 8 + q] = src[(size_t)k * 1024 + q];
        }
    }

    // --- GEMM roles ---
    const int s = tid >> 4;          // k-slice 0..15
    const int cov = tid & 15;
    const int bg = cov & 7;          // batch group (4 batches)
    const int cg = cov >> 3;         // col group (16 cols)
    const int b0 = bg * 4;
    const int c0 = cg * 16;
    const int kb = s * KSL;

    // --- gate-math roles ---
    const int up = tid >> 5;         // unit-in-CTA 0..7
    const int gb = tid & 31;         // batch 0..31
    const int ug = cu * 8 + up;      // global unit

    float c_state = 0.0f;

    __syncthreads();                 // weights ready

    for (int t = 0; t < TT; t++) {
        const float* __restrict__ hT = g_hT[t & 1];
        float* __restrict__ hTo = g_hT[(t + 1) & 1];

        // Prefetch zx for this step (hidden behind the GEMM)
        float4 zx4 = __ldcg((const float4*)&g_zx[((size_t)t * BB + gb) * NC + ug * 4]);

        // ---- GEMM: acc[b][cp] over k in [kb, kb+64) ----
        unsigned long long acc[4][8];
#pragma unroll
        for (int b = 0; b < 4; b++)
#pragma unroll
            for (int p = 0; p < 8; p++) acc[b][p] = 0ull;

        const float4* hp = (const float4*)(hT + (size_t)kb * 32 + b0);
        const ulonglong2* wrow0 = (const ulonglong2*)(ws + kb * 32 + c0);

        // Deep double-buffer: 8 k-iters per buffer -> ~580 cyc latency cover
        float4 bufA[8], bufB[8];
#pragma unroll
        for (int j = 0; j < 8; j++) bufA[j] = __ldcg(hp + (size_t)j * 8);

#pragma unroll
        for (int kc = 0; kc < KSL; kc += 16) {
#pragma unroll
            for (int j = 0; j < 8; j++) bufB[j] = __ldcg(hp + (size_t)(kc + 8 + j) * 8);
#pragma unroll
            for (int j = 0; j < 8; j++) {
                float4 hv = bufA[j];
                unsigned long long h0 = dup2(hv.x), h1 = dup2(hv.y);
                unsigned long long h2 = dup2(hv.z), h3 = dup2(hv.w);
                const ulonglong2* wr = wrow0 + (size_t)(kc + j) * 8;
#pragma unroll
                for (int q = 0; q < 4; q++) {
                    ulonglong2 w2 = wr[q];
                    fma2(acc[0][2 * q], h0, w2.x); fma2(acc[0][2 * q + 1], h0, w2.y);
                    fma2(acc[1][2 * q], h1, w2.x); fma2(acc[1][2 * q + 1], h1, w2.y);
                    fma2(acc[2][2 * q], h2, w2.x); fma2(acc[2][2 * q + 1], h2, w2.y);
                    fma2(acc[3][2 * q], h3, w2.x); fma2(acc[3][2 * q + 1], h3, w2.y);
                }
            }
            if (kc + 16 < KSL) {
#pragma unroll
                for (int j = 0; j < 8; j++) bufA[j] = __ldcg(hp + (size_t)(kc + 16 + j) * 8);
            }
#pragma unroll
            for (int j = 0; j < 8; j++) {
                float4 hv = bufB[j];
                unsigned long long h0 = dup2(hv.x), h1 = dup2(hv.y);
                unsigned long long h2 = dup2(hv.z), h3 = dup2(hv.w);
                const ulonglong2* wr = wrow0 + (size_t)(kc + 8 + j) * 8;
#pragma unroll
                for (int q = 0; q < 4; q++) {
                    ulonglong2 w2 = wr[q];
                    fma2(acc[0][2 * q], h0, w2.x); fma2(acc[0][2 * q + 1], h0, w2.y);
                    fma2(acc[1][2 * q], h1, w2.x); fma2(acc[1][2 * q + 1], h1, w2.y);
                    fma2(acc[2][2 * q], h2, w2.x); fma2(acc[2][2 * q + 1], h2, w2.y);
                    fma2(acc[3][2 * q], h3, w2.x); fma2(acc[3][2 * q + 1], h3, w2.y);
                }
            }
        }

        // ---- write partials: red[s][cp_global][b] ----
#pragma unroll
        for (int b = 0; b < 4; b++)
#pragma unroll
            for (int p = 0; p < 8; p++)
                red[((size_t)s * 16 + cg * 8 + p) * 32 + b0 + b] = acc[b][p];
        __syncthreads();

        // ---- reduce + gate math: thread = (unit up, batch gb) ----
        float h_new;
        {
            unsigned long long fiv = 0ull, gov = 0ull;
#pragma unroll
            for (int ss = 0; ss < NSLICE; ss++) {
                add2(fiv, red[((size_t)ss * 16 + 2 * up) * 32 + gb]);
                add2(gov, red[((size_t)ss * 16 + 2 * up + 1) * 32 + gb]);
            }
            float2 fi = unpack2(fiv);
            float2 go = unpack2(gov);
            float zf = fi.x + zx4.x;
            float zi = fi.y + zx4.y;
            float zg = go.x + zx4.z;
            float zo = go.y + zx4.w;

            float f = sigmoidf_(zf);
            float ii = sigmoidf_(zi);
            float g = tanhf_(zg);
            float o = sigmoidf_(zo);
            c_state = f * c_state + ii * g;
            h_new = o * tanhf_(c_state);

            __stcg(&hTo[ug * 32 + gb], h_new);
        }

        // ---- grid barrier (release/acquire; no L1-flushing membar) ----
        __syncthreads();   // all h stores issued, red consumed
        if (tid == 0) bar_arrive_release(&g_bar);

        // Overlap with barrier: out[] store (no cross-CTA consumer)
        out[((size_t)gb * TT + t) * UU + ug] = h_new;

        if (tid == 0) {
            unsigned target = (unsigned)NCTA * (unsigned)(t + 1);
            while (ld_acquire(&g_bar) < target) {}
        }
        __syncthreads();
    }
}

// ===========================================================================
// Launch
// ===========================================================================
extern "C" void kernel_launch(void* const* d_in, const int* in_sizes, int n_in,
                              void* d_out, int out_size) {
    const float* data = (const float*)d_in[0];
    const float* Wf = (const float*)d_in[1];
    const float* bf = (const float*)d_in[2];
    const float* Wi = (const float*)d_in[3];
    const float* bi = (const float*)d_in[4];
    const float* Wc = (const float*)d_in[5];
    const float* bc = (const float*)d_in[6];
    const float* Wo = (const float*)d_in[7];
    const float* bo = (const float*)d_in[8];
    float* out = (float*)d_out;

    prep_kernel<<<512, 256>>>(Wf, Wi, Wc, Wo, bf, bi, bc, bo);

    dim3 zgrid(TT * BB / ZBM, NC / ZBN);
    zx_kernel<<<zgrid, 256>>>(data);

    static int smem_set = 0;
    const int smem_bytes = 1024 * 32 * 4 + 16 * 16 * 32 * 8;  // 128KB + 64KB = 192KB
    if (!smem_set) {
        cudaFuncSetAttribute(lstm_persistent,
                             cudaFuncAttributeMaxDynamicSharedMemorySize, smem_bytes);
        smem_set = 1;
    }
    lstm_persistent<<<NCTA, 256, smem_bytes>>>(out);
}